// round 2
// baseline (speedup 1.0000x reference)
#include <cuda_runtime.h>
#include <cuda_bf16.h>
#include <cstdint>

#define SEQ   2048
#define BATCH 128
#define INDIM 128
#define HID   256

// Scratch for the precomputed input projection xin[s][b][h] (256 MB).
// __device__ global array = allowed scratch (no runtime allocation).
__device__ float g_xin[(size_t)SEQ * BATCH * HID];

// ---------------------------------------------------------------------------
// Kernel 1: xin = x @ W_in^T + b_in
//   A = x reshaped [M=SEQ*BATCH, K=128] (row-major, K contiguous)
//   W = W_in [N=256, K=128]            (row-major, K contiguous)
//   C = g_xin [M, N=256]
// Classic 128x128 tile, BK=16, 256 threads, 8x8 microtile.
// ---------------------------------------------------------------------------
#define GM_BM 128
#define GM_BN 128
#define GM_BK 16

__global__ __launch_bounds__(256) void xin_gemm_kernel(
    const float* __restrict__ X,
    const float* __restrict__ Win,
    const float* __restrict__ bin)
{
    __shared__ float As[GM_BK][GM_BM + 4];
    __shared__ float Bs[GM_BK][GM_BN + 4];

    const int tid = threadIdx.x;
    const size_t m0 = (size_t)blockIdx.x * GM_BM;
    const int    n0 = blockIdx.y * GM_BN;

    const int tx = tid & 15;   // 0..15 -> n micro
    const int ty = tid >> 4;   // 0..15 -> m micro

    const int lr = tid >> 2;          // 0..63  (row within tile)
    const int lc = (tid & 3) * 4;     // 0,4,8,12 (k offset)

    float acc[8][8];
#pragma unroll
    for (int i = 0; i < 8; i++)
#pragma unroll
        for (int jj = 0; jj < 8; jj++) acc[i][jj] = 0.0f;

#pragma unroll
    for (int k0 = 0; k0 < INDIM; k0 += GM_BK) {
        // global loads (row-major, K contiguous -> float4 along k)
        const float4 a0 = *(const float4*)&X[(m0 + lr) * INDIM + k0 + lc];
        const float4 a1 = *(const float4*)&X[(m0 + lr + 64) * INDIM + k0 + lc];
        const float4 w0 = *(const float4*)&Win[(size_t)(n0 + lr) * INDIM + k0 + lc];
        const float4 w1 = *(const float4*)&Win[(size_t)(n0 + lr + 64) * INDIM + k0 + lc];

        __syncthreads();   // previous iter's reads done before overwrite

        As[lc + 0][lr] = a0.x; As[lc + 1][lr] = a0.y;
        As[lc + 2][lr] = a0.z; As[lc + 3][lr] = a0.w;
        As[lc + 0][lr + 64] = a1.x; As[lc + 1][lr + 64] = a1.y;
        As[lc + 2][lr + 64] = a1.z; As[lc + 3][lr + 64] = a1.w;

        Bs[lc + 0][lr] = w0.x; Bs[lc + 1][lr] = w0.y;
        Bs[lc + 2][lr] = w0.z; Bs[lc + 3][lr] = w0.w;
        Bs[lc + 0][lr + 64] = w1.x; Bs[lc + 1][lr + 64] = w1.y;
        Bs[lc + 2][lr + 64] = w1.z; Bs[lc + 3][lr + 64] = w1.w;

        __syncthreads();

#pragma unroll
        for (int k = 0; k < GM_BK; k++) {
            float ar[8], br[8];
            float4 t;
            t = *(const float4*)&As[k][ty * 8 + 0];
            ar[0] = t.x; ar[1] = t.y; ar[2] = t.z; ar[3] = t.w;
            t = *(const float4*)&As[k][ty * 8 + 4];
            ar[4] = t.x; ar[5] = t.y; ar[6] = t.z; ar[7] = t.w;
            t = *(const float4*)&Bs[k][tx * 8 + 0];
            br[0] = t.x; br[1] = t.y; br[2] = t.z; br[3] = t.w;
            t = *(const float4*)&Bs[k][tx * 8 + 4];
            br[4] = t.x; br[5] = t.y; br[6] = t.z; br[7] = t.w;
#pragma unroll
            for (int i = 0; i < 8; i++)
#pragma unroll
                for (int jj = 0; jj < 8; jj++)
                    acc[i][jj] = fmaf(ar[i], br[jj], acc[i][jj]);
        }
    }

    // epilogue: add b_in, store to g_xin (n contiguous)
    float bn[8];
#pragma unroll
    for (int jj = 0; jj < 8; jj++) bn[jj] = bin[n0 + tx * 8 + jj];

#pragma unroll
    for (int i = 0; i < 8; i++) {
        const size_t m = m0 + ty * 8 + i;
        float4 o0, o1;
        o0.x = acc[i][0] + bn[0]; o0.y = acc[i][1] + bn[1];
        o0.z = acc[i][2] + bn[2]; o0.w = acc[i][3] + bn[3];
        o1.x = acc[i][4] + bn[4]; o1.y = acc[i][5] + bn[5];
        o1.z = acc[i][6] + bn[6]; o1.w = acc[i][7] + bn[7];
        *(float4*)&g_xin[m * HID + n0 + tx * 8 + 0] = o0;
        *(float4*)&g_xin[m * HID + n0 + tx * 8 + 4] = o1;
    }
}

// ---------------------------------------------------------------------------
// Kernel 2: persistent batch-parallel scan.
// 128 CTAs (one per batch row), 256 threads (one per hidden unit j).
// W_h[j, 0:128]   -> shared memory, stored as float4 groups WS4[g*256+j]
//                    = {W[j][4g..4g+3]}, conflict-free across lanes.
// W_h[j, 128:256] -> 128 registers per thread (32K regs/CTA, fits RF).
// h state double-buffered in shared memory; one __syncthreads per step.
// ---------------------------------------------------------------------------
__global__ __launch_bounds__(256, 1) void ctrnn_scan_kernel(
    const float* __restrict__ h0,
    const float* __restrict__ Wh,
    const float* __restrict__ bh,
    float* __restrict__ out,
    long long out_size)
{
    extern __shared__ float4 WS4[];          // [32 * 256] float4 = 128 KB
    __shared__ float4 hbuf[2][HID / 4];      // double-buffered h (2 KB)

    const int j = threadIdx.x;               // hidden index 0..255
    const int b = blockIdx.x;                // batch row 0..127

    // Load smem half of W (k in [0,128)): one-time, uncoalesced OK.
#pragma unroll
    for (int g = 0; g < 32; g++) {
        WS4[g * HID + j] = *(const float4*)&Wh[(size_t)j * HID + g * 4];
    }

    // Register half of W (k in [128,256)).
    float wreg[128];
#pragma unroll
    for (int i = 0; i < 128; i++) wreg[i] = Wh[(size_t)j * HID + 128 + i];

    float hcur = h0[(size_t)b * HID + j];
    ((float*)hbuf[0])[j] = hcur;
    const float bhj = bh[j];
    __syncthreads();

    const float* __restrict__ xin_bj = g_xin + (size_t)b * HID + j;
    float* __restrict__ out_bj = out + (size_t)b * HID + j;
    const size_t step_stride = (size_t)BATCH * HID;

    int p = 0;
    for (int t = 0; t < SEQ; t++) {
        // input projection value for this (t, b, j) — issue early
        const float xv = __ldg(&xin_bj[(size_t)t * step_stride]);

        const float4* __restrict__ hc = hbuf[p];
        float y0 = 0.0f, y1 = 0.0f, y2 = 0.0f, y3 = 0.0f;

        // k in [0,128): W from smem
#pragma unroll
        for (int g = 0; g < 32; g++) {
            const float4 w  = WS4[g * HID + j];
            const float4 hv = hc[g];
            y0 = fmaf(w.x, hv.x, y0);
            y1 = fmaf(w.y, hv.y, y1);
            y2 = fmaf(w.z, hv.z, y2);
            y3 = fmaf(w.w, hv.w, y3);
        }
        // k in [128,256): W from registers (must be fully unrolled)
#pragma unroll
        for (int g = 0; g < 32; g++) {
            const float4 hv = hc[32 + g];
            y0 = fmaf(wreg[g * 4 + 0], hv.x, y0);
            y1 = fmaf(wreg[g * 4 + 1], hv.y, y1);
            y2 = fmaf(wreg[g * 4 + 2], hv.z, y2);
            y3 = fmaf(wreg[g * 4 + 3], hv.w, y3);
        }

        const float y  = ((y0 + y1) + (y2 + y3)) + xv + bhj;
        const float hn = fmaxf(y, 0.0f) * 0.1f + 0.9f * hcur;
        hcur = hn;

        ((float*)hbuf[p ^ 1])[j] = hn;            // publish next-state
        out_bj[(size_t)t * step_stride] = hn;     // coalesced output write
        p ^= 1;
        __syncthreads();                           // one barrier per step
    }

    // h_final appended after outputs (reference returns (outputs, h_final))
    const long long main_elems = (long long)SEQ * BATCH * HID;
    if (out_size >= main_elems + (long long)BATCH * HID) {
        out[main_elems + (size_t)b * HID + j] = hcur;
    }
}

// ---------------------------------------------------------------------------
// Launcher
// Inputs (metadata order): x, h0, W_in, b_in, W_h, b_h
// ---------------------------------------------------------------------------
extern "C" void kernel_launch(void* const* d_in, const int* in_sizes, int n_in,
                              void* d_out, int out_size)
{
    const float* x    = (const float*)d_in[0];
    const float* h0   = (const float*)d_in[1];
    const float* Win  = (const float*)d_in[2];
    const float* bin  = (const float*)d_in[3];
    const float* Wh   = (const float*)d_in[4];
    const float* bhp  = (const float*)d_in[5];
    float* out = (float*)d_out;

    // opt into >48 KB dynamic smem for the scan kernel (idempotent, host-side)
    cudaFuncSetAttribute(ctrnn_scan_kernel,
                         cudaFuncAttributeMaxDynamicSharedMemorySize,
                         32 * HID * (int)sizeof(float4));

    // Kernel 1: input projection for all timesteps
    dim3 g1((SEQ * BATCH) / GM_BM, HID / GM_BN);
    xin_gemm_kernel<<<g1, 256>>>(x, Win, bin);

    // Kernel 2: persistent sequential scan, batch-parallel
    ctrnn_scan_kernel<<<BATCH, HID, 32 * HID * sizeof(float4)>>>(
        h0, Wh, bhp, out, (long long)out_size);
}

// round 3
// speedup vs baseline: 1.1149x; 1.1149x over previous
#include <cuda_runtime.h>
#include <cuda_bf16.h>
#include <cstdint>

#define SEQ   2048
#define BATCH 128
#define INDIM 128
#define HID   256

// Scratch for the precomputed input projection xin[s][b][h] (256 MB).
__device__ float g_xin[(size_t)SEQ * BATCH * HID];

// ---------------------------------------------------------------------------
// Packed fp32x2 helpers (PTX-only FFMA2 form; ptxas never emits it from C++)
// ---------------------------------------------------------------------------
__device__ __forceinline__ void ffma2(unsigned long long& d,
                                      unsigned long long a,
                                      unsigned long long b) {
    asm("fma.rn.f32x2 %0, %1, %2, %0;" : "+l"(d) : "l"(a), "l"(b));
}
__device__ __forceinline__ unsigned long long dup2(float x) {
    unsigned long long r;
    asm("mov.b64 %0, {%1, %1};" : "=l"(r) : "f"(x));
    return r;
}
__device__ __forceinline__ float sum2(unsigned long long v) {
    return __uint_as_float((unsigned)v) + __uint_as_float((unsigned)(v >> 32));
}

// ---------------------------------------------------------------------------
// Kernel 1: xin = x @ W_in^T + b_in   (packed-f32x2 microkernel)
//   A = x [M=SEQ*BATCH, K=128]  row-major
//   W = W_in [N=256, K=128]     row-major
// 128x128 tile, BK=16, 256 threads, 8x8 microtile (n packed in pairs).
// ---------------------------------------------------------------------------
#define GM_BM 128
#define GM_BN 128
#define GM_BK 16

__global__ __launch_bounds__(256) void xin_gemm_kernel(
    const float* __restrict__ X,
    const float* __restrict__ Win,
    const float* __restrict__ bin)
{
    __shared__ float As[GM_BK][GM_BM + 8];   // +8 keeps rows 16B-aligned
    __shared__ float Bs[GM_BK][GM_BN + 8];

    const int tid = threadIdx.x;
    const size_t m0 = (size_t)blockIdx.x * GM_BM;
    const int    n0 = blockIdx.y * GM_BN;

    const int tx = tid & 15;   // n micro
    const int ty = tid >> 4;   // m micro

    const int lr = tid >> 2;          // 0..63
    const int lc = (tid & 3) * 4;     // 0,4,8,12

    unsigned long long acc[8][4];     // 8 m-rows x 4 packed n-pairs
#pragma unroll
    for (int i = 0; i < 8; i++)
#pragma unroll
        for (int jp = 0; jp < 4; jp++) acc[i][jp] = 0ull;

#pragma unroll
    for (int k0 = 0; k0 < INDIM; k0 += GM_BK) {
        const float4 a0 = *(const float4*)&X[(m0 + lr) * INDIM + k0 + lc];
        const float4 a1 = *(const float4*)&X[(m0 + lr + 64) * INDIM + k0 + lc];
        const float4 w0 = *(const float4*)&Win[(size_t)(n0 + lr) * INDIM + k0 + lc];
        const float4 w1 = *(const float4*)&Win[(size_t)(n0 + lr + 64) * INDIM + k0 + lc];

        __syncthreads();

        As[lc + 0][lr] = a0.x; As[lc + 1][lr] = a0.y;
        As[lc + 2][lr] = a0.z; As[lc + 3][lr] = a0.w;
        As[lc + 0][lr + 64] = a1.x; As[lc + 1][lr + 64] = a1.y;
        As[lc + 2][lr + 64] = a1.z; As[lc + 3][lr + 64] = a1.w;

        Bs[lc + 0][lr] = w0.x; Bs[lc + 1][lr] = w0.y;
        Bs[lc + 2][lr] = w0.z; Bs[lc + 3][lr] = w0.w;
        Bs[lc + 0][lr + 64] = w1.x; Bs[lc + 1][lr + 64] = w1.y;
        Bs[lc + 2][lr + 64] = w1.z; Bs[lc + 3][lr + 64] = w1.w;

        __syncthreads();

#pragma unroll
        for (int k = 0; k < GM_BK; k++) {
            float ar[8];
            float4 t;
            t = *(const float4*)&As[k][ty * 8 + 0];
            ar[0] = t.x; ar[1] = t.y; ar[2] = t.z; ar[3] = t.w;
            t = *(const float4*)&As[k][ty * 8 + 4];
            ar[4] = t.x; ar[5] = t.y; ar[6] = t.z; ar[7] = t.w;

            // 8 contiguous n-values = 4 packed pairs (rows are 16B aligned)
            const ulonglong2 b01 = *(const ulonglong2*)&Bs[k][tx * 8 + 0];
            const ulonglong2 b23 = *(const ulonglong2*)&Bs[k][tx * 8 + 4];

#pragma unroll
            for (int i = 0; i < 8; i++) {
                const unsigned long long ad = dup2(ar[i]);
                ffma2(acc[i][0], ad, b01.x);
                ffma2(acc[i][1], ad, b01.y);
                ffma2(acc[i][2], ad, b23.x);
                ffma2(acc[i][3], ad, b23.y);
            }
        }
    }

    float bn[8];
#pragma unroll
    for (int jj = 0; jj < 8; jj++) bn[jj] = bin[n0 + tx * 8 + jj];

#pragma unroll
    for (int i = 0; i < 8; i++) {
        const size_t m = m0 + ty * 8 + i;
        float4 o0, o1;
        o0.x = __uint_as_float((unsigned)acc[i][0]) + bn[0];
        o0.y = __uint_as_float((unsigned)(acc[i][0] >> 32)) + bn[1];
        o0.z = __uint_as_float((unsigned)acc[i][1]) + bn[2];
        o0.w = __uint_as_float((unsigned)(acc[i][1] >> 32)) + bn[3];
        o1.x = __uint_as_float((unsigned)acc[i][2]) + bn[4];
        o1.y = __uint_as_float((unsigned)(acc[i][2] >> 32)) + bn[5];
        o1.z = __uint_as_float((unsigned)acc[i][3]) + bn[6];
        o1.w = __uint_as_float((unsigned)(acc[i][3] >> 32)) + bn[7];
        *(float4*)&g_xin[m * HID + n0 + tx * 8 + 0] = o0;
        *(float4*)&g_xin[m * HID + n0 + tx * 8 + 4] = o1;
    }
}

// ---------------------------------------------------------------------------
// Kernel 2: persistent batch-parallel scan (packed f32x2).
// 128 CTAs (1 batch row each), 256 threads (1 hidden unit each).
//   W_h[j, 0:96)    -> shared memory (96 KB), stored as packed ulonglong2
//   W_h[j, 96:256)  -> 80 packed u64 registers per thread (160 floats)
// h double-buffered in smem; one __syncthreads per step; xin prefetched.
// ---------------------------------------------------------------------------
#define SMEM_G 24          // smem k-groups of 4 floats -> k in [0, 96)
#define REG_P  80          // register packed pairs     -> k in [96, 256)

__global__ __launch_bounds__(256, 1) void ctrnn_scan_kernel(
    const float* __restrict__ h0,
    const float* __restrict__ Wh,
    const float* __restrict__ bh,
    float* __restrict__ out,
    long long out_size)
{
    extern __shared__ ulonglong2 WS[];        // [SMEM_G * 256] = 96 KB
    __shared__ float4 hbuf[2][HID / 4];       // double-buffered h

    const int j = threadIdx.x;
    const int b = blockIdx.x;

    const float* __restrict__ wrow = Wh + (size_t)j * HID;

    // smem half of W: k in [0, 96)
#pragma unroll
    for (int g = 0; g < SMEM_G; g++)
        WS[g * HID + j] = ((const ulonglong2*)wrow)[g];

    // register half of W: k in [96, 256) as 80 packed pairs
    unsigned long long wreg[REG_P];
#pragma unroll
    for (int i = 0; i < REG_P; i++)
        wreg[i] = ((const unsigned long long*)(wrow + 4 * SMEM_G))[i];

    float hcur = h0[(size_t)b * HID + j];
    ((float*)hbuf[0])[j] = hcur;
    const float bhj = bh[j];
    __syncthreads();

    const float* __restrict__ xin_bj = g_xin + (size_t)b * HID + j;
    float* __restrict__ out_bj = out + (size_t)b * HID + j;
    const size_t step_stride = (size_t)BATCH * HID;

    float xv = __ldg(&xin_bj[0]);             // prefetch for t = 0

    int p = 0;
    for (int t = 0; t < SEQ; t++) {
        // prefetch xin for t+1 so DRAM latency overlaps the FMA body
        const int tn = (t + 1 < SEQ) ? (t + 1) : t;
        const float xv_next = __ldg(&xin_bj[(size_t)tn * step_stride]);

        const ulonglong2* __restrict__ hc = (const ulonglong2*)hbuf[p];

        unsigned long long a0 = 0ull, a1 = 0ull, a2 = 0ull, a3 = 0ull;

        // k in [0, 96): W from smem (2 packed pairs per group)
#pragma unroll
        for (int g = 0; g < SMEM_G; g++) {
            const ulonglong2 w  = WS[g * HID + j];
            const ulonglong2 hv = hc[g];
            if (g & 1) { ffma2(a2, w.x, hv.x); ffma2(a3, w.y, hv.y); }
            else       { ffma2(a0, w.x, hv.x); ffma2(a1, w.y, hv.y); }
        }
        // k in [96, 256): W from registers
#pragma unroll
        for (int g = 0; g < 64 - SMEM_G; g++) {
            const ulonglong2 hv = hc[SMEM_G + g];
            if (g & 1) { ffma2(a2, wreg[2 * g], hv.x); ffma2(a3, wreg[2 * g + 1], hv.y); }
            else       { ffma2(a0, wreg[2 * g], hv.x); ffma2(a1, wreg[2 * g + 1], hv.y); }
        }

        const float y = ((sum2(a0) + sum2(a1)) + (sum2(a2) + sum2(a3))) + xv + bhj;
        const float hn = fmaxf(y, 0.0f) * 0.1f + 0.9f * hcur;
        hcur = hn;
        xv = xv_next;

        ((float*)hbuf[p ^ 1])[j] = hn;
        out_bj[(size_t)t * step_stride] = hn;
        p ^= 1;
        __syncthreads();
    }

    const long long main_elems = (long long)SEQ * BATCH * HID;
    if (out_size >= main_elems + (long long)BATCH * HID) {
        out[main_elems + (size_t)b * HID + j] = hcur;
    }
}

// ---------------------------------------------------------------------------
// Launcher.  Inputs (metadata order): x, h0, W_in, b_in, W_h, b_h
// ---------------------------------------------------------------------------
extern "C" void kernel_launch(void* const* d_in, const int* in_sizes, int n_in,
                              void* d_out, int out_size)
{
    const float* x    = (const float*)d_in[0];
    const float* h0   = (const float*)d_in[1];
    const float* Win  = (const float*)d_in[2];
    const float* bin  = (const float*)d_in[3];
    const float* Wh   = (const float*)d_in[4];
    const float* bhp  = (const float*)d_in[5];
    float* out = (float*)d_out;

    const int scan_smem = SMEM_G * HID * (int)sizeof(ulonglong2);   // 96 KB
    cudaFuncSetAttribute(ctrnn_scan_kernel,
                         cudaFuncAttributeMaxDynamicSharedMemorySize,
                         scan_smem);

    dim3 g1((SEQ * BATCH) / GM_BM, HID / GM_BN);
    xin_gemm_kernel<<<g1, 256>>>(x, Win, bin);

    ctrnn_scan_kernel<<<BATCH, HID, scan_smem>>>(
        h0, Wh, bhp, out, (long long)out_size);
}

// round 4
// speedup vs baseline: 1.6267x; 1.4590x over previous
#include <cuda_runtime.h>
#include <cuda_bf16.h>
#include <cstdint>

#define SEQ   2048
#define BATCH 128
#define INDIM 128
#define HID   256

// Scratch for the precomputed input projection xin[s][b][h] (256 MB).
__device__ float g_xin[(size_t)SEQ * BATCH * HID];

// ---------------------------------------------------------------------------
// Packed fp32x2 helpers
// ---------------------------------------------------------------------------
__device__ __forceinline__ void ffma2(unsigned long long& d,
                                      unsigned long long a,
                                      unsigned long long b) {
    asm("fma.rn.f32x2 %0, %1, %2, %0;" : "+l"(d) : "l"(a), "l"(b));
}
__device__ __forceinline__ unsigned long long dup2(float x) {
    unsigned long long r;
    asm("mov.b64 %0, {%1, %1};" : "=l"(r) : "f"(x));
    return r;
}
__device__ __forceinline__ float sum2(unsigned long long v) {
    return __uint_as_float((unsigned)v) + __uint_as_float((unsigned)(v >> 32));
}

// ---------------------------------------------------------------------------
// Kernel 1: xin = x @ W_in^T + b_in   (packed-f32x2 microkernel) — unchanged
// ---------------------------------------------------------------------------
#define GM_BM 128
#define GM_BN 128
#define GM_BK 16

__global__ __launch_bounds__(256) void xin_gemm_kernel(
    const float* __restrict__ X,
    const float* __restrict__ Win,
    const float* __restrict__ bin)
{
    __shared__ float As[GM_BK][GM_BM + 8];
    __shared__ float Bs[GM_BK][GM_BN + 8];

    const int tid = threadIdx.x;
    const size_t m0 = (size_t)blockIdx.x * GM_BM;
    const int    n0 = blockIdx.y * GM_BN;

    const int tx = tid & 15;
    const int ty = tid >> 4;

    const int lr = tid >> 2;
    const int lc = (tid & 3) * 4;

    unsigned long long acc[8][4];
#pragma unroll
    for (int i = 0; i < 8; i++)
#pragma unroll
        for (int jp = 0; jp < 4; jp++) acc[i][jp] = 0ull;

#pragma unroll
    for (int k0 = 0; k0 < INDIM; k0 += GM_BK) {
        const float4 a0 = *(const float4*)&X[(m0 + lr) * INDIM + k0 + lc];
        const float4 a1 = *(const float4*)&X[(m0 + lr + 64) * INDIM + k0 + lc];
        const float4 w0 = *(const float4*)&Win[(size_t)(n0 + lr) * INDIM + k0 + lc];
        const float4 w1 = *(const float4*)&Win[(size_t)(n0 + lr + 64) * INDIM + k0 + lc];

        __syncthreads();

        As[lc + 0][lr] = a0.x; As[lc + 1][lr] = a0.y;
        As[lc + 2][lr] = a0.z; As[lc + 3][lr] = a0.w;
        As[lc + 0][lr + 64] = a1.x; As[lc + 1][lr + 64] = a1.y;
        As[lc + 2][lr + 64] = a1.z; As[lc + 3][lr + 64] = a1.w;

        Bs[lc + 0][lr] = w0.x; Bs[lc + 1][lr] = w0.y;
        Bs[lc + 2][lr] = w0.z; Bs[lc + 3][lr] = w0.w;
        Bs[lc + 0][lr + 64] = w1.x; Bs[lc + 1][lr + 64] = w1.y;
        Bs[lc + 2][lr + 64] = w1.z; Bs[lc + 3][lr + 64] = w1.w;

        __syncthreads();

#pragma unroll
        for (int k = 0; k < GM_BK; k++) {
            float ar[8];
            float4 t;
            t = *(const float4*)&As[k][ty * 8 + 0];
            ar[0] = t.x; ar[1] = t.y; ar[2] = t.z; ar[3] = t.w;
            t = *(const float4*)&As[k][ty * 8 + 4];
            ar[4] = t.x; ar[5] = t.y; ar[6] = t.z; ar[7] = t.w;

            const ulonglong2 b01 = *(const ulonglong2*)&Bs[k][tx * 8 + 0];
            const ulonglong2 b23 = *(const ulonglong2*)&Bs[k][tx * 8 + 4];

#pragma unroll
            for (int i = 0; i < 8; i++) {
                const unsigned long long ad = dup2(ar[i]);
                ffma2(acc[i][0], ad, b01.x);
                ffma2(acc[i][1], ad, b01.y);
                ffma2(acc[i][2], ad, b23.x);
                ffma2(acc[i][3], ad, b23.y);
            }
        }
    }

    float bn[8];
#pragma unroll
    for (int jj = 0; jj < 8; jj++) bn[jj] = bin[n0 + tx * 8 + jj];

#pragma unroll
    for (int i = 0; i < 8; i++) {
        const size_t m = m0 + ty * 8 + i;
        float4 o0, o1;
        o0.x = __uint_as_float((unsigned)acc[i][0]) + bn[0];
        o0.y = __uint_as_float((unsigned)(acc[i][0] >> 32)) + bn[1];
        o0.z = __uint_as_float((unsigned)acc[i][1]) + bn[2];
        o0.w = __uint_as_float((unsigned)(acc[i][1] >> 32)) + bn[3];
        o1.x = __uint_as_float((unsigned)acc[i][2]) + bn[4];
        o1.y = __uint_as_float((unsigned)(acc[i][2] >> 32)) + bn[5];
        o1.z = __uint_as_float((unsigned)acc[i][3]) + bn[6];
        o1.w = __uint_as_float((unsigned)(acc[i][3] >> 32)) + bn[7];
        *(float4*)&g_xin[m * HID + n0 + tx * 8 + 0] = o0;
        *(float4*)&g_xin[m * HID + n0 + tx * 8 + 4] = o1;
    }
}

// ---------------------------------------------------------------------------
// Kernel 2: persistent scan, lane-level k-split.
// 128 CTAs x 256 threads. Warp w owns outputs j in [32w, 32w+32).
// Lane = (g, ji): g = lane>>3 (k-group 0..3), ji = lane&7.
// Lane computes 4 outputs j = 32w + 8m + ji (m = 0..3), partial over its
// k-subset {32L + 8g + e : L=0..7, e=0..7} (32B-interleaved inside 128B lines
// so the 4 k-groups' h loads hit ONE line per instruction -> 1 wavefront).
// W for k-lines 0..1 in smem (thread-private chunks), lines 2..7 in registers.
// Dot product finished with 2 butterfly shuffles over the k-group lane bits.
// ---------------------------------------------------------------------------
__global__ __launch_bounds__(256, 1) void ctrnn_scan_kernel(
    const float* __restrict__ h0,
    const float* __restrict__ Wh,
    const float* __restrict__ bh,
    float* __restrict__ out,
    long long out_size)
{
    extern __shared__ float4 Wsm4[];                 // 4096 * 16B = 64 KB
    __shared__ __align__(128) float hbuf[2][HID];    // double-buffered h

    const int tid  = threadIdx.x;
    const int b    = blockIdx.x;
    const int w    = tid >> 5;
    const int lane = tid & 31;
    const int g    = lane >> 3;
    const int ji   = lane & 7;

    // thread-private Wsm chunk base (float4 units); chunks read only by owner
    const int base4 = w * 512 + g * 8 + ji;

    // ---- stage W: smem part (k-lines 0..1) ----
#pragma unroll
    for (int m = 0; m < 4; m++) {
        const int j = 32 * w + 8 * m + ji;
        const float* wr = Wh + (size_t)j * HID;
#pragma unroll
        for (int L = 0; L < 2; L++)
#pragma unroll
            for (int h2 = 0; h2 < 2; h2++)
                Wsm4[base4 + (m * 4 + L * 2 + h2) * 32] =
                    *(const float4*)&wr[32 * L + 8 * g + 4 * h2];
    }

    // ---- stage W: register part (k-lines 2..7), packed fp32 pairs ----
    unsigned long long wreg[4][6][4];
#pragma unroll
    for (int m = 0; m < 4; m++) {
        const int j = 32 * w + 8 * m + ji;
        const float* wr = Wh + (size_t)j * HID;
#pragma unroll
        for (int L = 0; L < 6; L++)
#pragma unroll
            for (int p = 0; p < 4; p++)
                wreg[m][L][p] =
                    *(const unsigned long long*)&wr[32 * (L + 2) + 8 * g + 2 * p];
    }

    float bhm[4], hprev[4], xv[4];
#pragma unroll
    for (int m = 0; m < 4; m++) bhm[m] = bh[32 * w + 8 * m + ji];

    const float* __restrict__ xin_b = g_xin + (size_t)b * HID;
    float* __restrict__ out_b = out + (size_t)b * HID;
    const size_t ss = (size_t)BATCH * HID;

    if (g == 0) {
#pragma unroll
        for (int m = 0; m < 4; m++) {
            const int j = 32 * w + 8 * m + ji;
            hprev[m] = h0[(size_t)b * HID + j];
            xv[m] = __ldg(&xin_b[j]);
        }
    }
    hbuf[0][tid] = h0[(size_t)b * HID + tid];
    __syncthreads();

    int p = 0;
    for (int t = 0; t < SEQ; t++) {
        const ulonglong2* __restrict__ C2 = (const ulonglong2*)hbuf[p];
        float* __restrict__ nxt = hbuf[p ^ 1];

        // prefetch next step's xin (DRAM latency overlaps FMA body)
        float xvn[4];
        if (g == 0) {
            const int tn = (t + 1 < SEQ) ? (t + 1) : t;
#pragma unroll
            for (int m = 0; m < 4; m++)
                xvn[m] = __ldg(&xin_b[(size_t)tn * ss + 32 * w + 8 * m + ji]);
        }

        unsigned long long acc[4] = {0ull, 0ull, 0ull, 0ull};

#pragma unroll
        for (int L = 0; L < 8; L++) {
            // lane's 8 h values on line L: one 128B line across all 4 k-groups
            const ulonglong2 ca = C2[8 * L + 2 * g + 0];
            const ulonglong2 cb = C2[8 * L + 2 * g + 1];

            if (L < 2) {
#pragma unroll
                for (int m = 0; m < 4; m++) {
                    const ulonglong2 wa =
                        *(const ulonglong2*)&Wsm4[base4 + (m * 4 + L * 2 + 0) * 32];
                    const ulonglong2 wb =
                        *(const ulonglong2*)&Wsm4[base4 + (m * 4 + L * 2 + 1) * 32];
                    ffma2(acc[m], wa.x, ca.x);
                    ffma2(acc[m], wa.y, ca.y);
                    ffma2(acc[m], wb.x, cb.x);
                    ffma2(acc[m], wb.y, cb.y);
                }
            } else {
#pragma unroll
                for (int m = 0; m < 4; m++) {
                    ffma2(acc[m], wreg[m][L - 2][0], ca.x);
                    ffma2(acc[m], wreg[m][L - 2][1], ca.y);
                    ffma2(acc[m], wreg[m][L - 2][2], cb.x);
                    ffma2(acc[m], wreg[m][L - 2][3], cb.y);
                }
            }
        }

        // reduce across the 4 k-groups (lane bits 3,4)
        float s[4];
#pragma unroll
        for (int m = 0; m < 4; m++) {
            float v = sum2(acc[m]);
            v += __shfl_xor_sync(0xffffffffu, v, 8, 32);
            v += __shfl_xor_sync(0xffffffffu, v, 16, 32);
            s[m] = v;
        }

        if (g == 0) {
#pragma unroll
            for (int m = 0; m < 4; m++) {
                const int j = 32 * w + 8 * m + ji;
                const float y  = s[m] + xv[m] + bhm[m];
                const float hn = fmaf(fmaxf(y, 0.0f), 0.1f, 0.9f * hprev[m]);
                hprev[m] = hn;
                nxt[j] = hn;
                out_b[(size_t)t * ss + j] = hn;
                xv[m] = xvn[m];
            }
        }
        p ^= 1;
        __syncthreads();
    }

    // h_final appended after outputs
    const long long main_elems = (long long)SEQ * BATCH * HID;
    if (g == 0 && out_size >= main_elems + (long long)BATCH * HID) {
#pragma unroll
        for (int m = 0; m < 4; m++)
            out[main_elems + (size_t)b * HID + 32 * w + 8 * m + ji] = hprev[m];
    }
}

// ---------------------------------------------------------------------------
// Launcher.  Inputs (metadata order): x, h0, W_in, b_in, W_h, b_h
// ---------------------------------------------------------------------------
extern "C" void kernel_launch(void* const* d_in, const int* in_sizes, int n_in,
                              void* d_out, int out_size)
{
    const float* x    = (const float*)d_in[0];
    const float* h0   = (const float*)d_in[1];
    const float* Win  = (const float*)d_in[2];
    const float* bin  = (const float*)d_in[3];
    const float* Wh   = (const float*)d_in[4];
    const float* bhp  = (const float*)d_in[5];
    float* out = (float*)d_out;

    const int scan_smem = 4096 * (int)sizeof(float4);   // 64 KB
    cudaFuncSetAttribute(ctrnn_scan_kernel,
                         cudaFuncAttributeMaxDynamicSharedMemorySize,
                         scan_smem);

    dim3 g1((SEQ * BATCH) / GM_BM, HID / GM_BN);
    xin_gemm_kernel<<<g1, 256>>>(x, Win, bin);

    ctrnn_scan_kernel<<<BATCH, HID, scan_smem>>>(
        h0, Wh, bhp, out, (long long)out_size);
}